// round 2
// baseline (speedup 1.0000x reference)
#include <cuda_runtime.h>
#include <stdint.h>

// Problem constants
#define TT   384      // num_thetas (= n1 = n2)
#define NN   384      // points per space
#define RR   384      // resolution
#define D1   128
#define D2   32
#define SZ1  (D1*TT)  // 49152
#define SZ2  (D2*TT)  // 12288
#define SCALE 500.0f

// Scratch (static device globals; no allocation allowed)
__device__ float g_v1[SZ1];
__device__ float g_v2[SZ2];
__device__ float g_invnorm[2*TT];
__device__ float g_nh1[TT*NN];   // transposed: [t][n]
__device__ float g_nh2[TT*NN];
__device__ float g_loss;

// ---------------------------------------------------------------------------
// Threefry2x32, key = (0, 42)  (jax.random.key(42))
// ---------------------------------------------------------------------------
__device__ __forceinline__ uint32_t rotl32(uint32_t x, int d) {
    return (x << d) | (x >> (32 - d));
}

__device__ __forceinline__ void threefry_0_42(uint32_t x0, uint32_t x1,
                                              uint32_t& o0, uint32_t& o1) {
    const uint32_t ks0 = 0u;
    const uint32_t ks1 = 42u;
    const uint32_t ks2 = 0u ^ 42u ^ 0x1BD11BDAu;
    x0 += ks0; x1 += ks1;
#define TF_R4(a,b,c,d)                               \
    x0 += x1; x1 = rotl32(x1,(a)); x1 ^= x0;          \
    x0 += x1; x1 = rotl32(x1,(b)); x1 ^= x0;          \
    x0 += x1; x1 = rotl32(x1,(c)); x1 ^= x0;          \
    x0 += x1; x1 = rotl32(x1,(d)); x1 ^= x0;
    TF_R4(13,15,26,6)   x0 += ks1; x1 += ks2 + 1u;
    TF_R4(17,29,16,24)  x0 += ks2; x1 += ks0 + 2u;
    TF_R4(13,15,26,6)   x0 += ks0; x1 += ks1 + 3u;
    TF_R4(17,29,16,24)  x0 += ks1; x1 += ks2 + 4u;
    TF_R4(13,15,26,6)   x0 += ks2; x1 += ks0 + 5u;
#undef TF_R4
    o0 = x0; o1 = x1;
}

// XLA ErfInv (float32 polynomial) — matches lax.erf_inv lowering
__device__ __forceinline__ float erfinv_xla(float x) {
    float w = -log1pf(-x * x);
    float p;
    if (w < 5.0f) {
        w -= 2.5f;
        p = 2.81022636e-08f;
        p = fmaf(p, w, 3.43273939e-07f);
        p = fmaf(p, w, -3.5233877e-06f);
        p = fmaf(p, w, -4.39150654e-06f);
        p = fmaf(p, w, 0.00021858087f);
        p = fmaf(p, w, -0.00125372503f);
        p = fmaf(p, w, -0.00417768164f);
        p = fmaf(p, w, 0.246640727f);
        p = fmaf(p, w, 1.50140941f);
    } else {
        w = sqrtf(w) - 3.0f;
        p = -0.000200214257f;
        p = fmaf(p, w, 0.000100950558f);
        p = fmaf(p, w, 0.00134934322f);
        p = fmaf(p, w, -0.00367342844f);
        p = fmaf(p, w, 0.00573950773f);
        p = fmaf(p, w, -0.0076224613f);
        p = fmaf(p, w, 0.00943887047f);
        p = fmaf(p, w, 1.00167406f);
        p = fmaf(p, w, 2.83297682f);
    }
    return p * x;
}

// jax.random.normal: uniform(lo=nextafter(-1,0), hi=1) -> sqrt(2)*erfinv(u)
__device__ __forceinline__ float bits_to_normal(uint32_t b) {
    float f = __uint_as_float((b >> 9) | 0x3F800000u) - 1.0f;   // [0,1)
    const float lo = -0.99999994f;                               // nextafter(-1,0)
    const float span = 1.0f - lo;                                // = 2.0f in f32
    float u = fmaf(f, span, lo);
    u = fmaxf(lo, u);
    return 1.41421356f * erfinv_xla(u);   // sqrt(2) in f32
}

// ---------------------------------------------------------------------------
// 1) Generate direction matrices — PARTITIONABLE threefry (JAX >= 0.4.36
//    default): per flat element i, counter = uint64(i) -> (hi=0, lo=i);
//    32-bit draw = o0 ^ o1.
// ---------------------------------------------------------------------------
__global__ void gen_dirs_kernel() {
    int i = blockIdx.x * blockDim.x + threadIdx.x;
    if (i < SZ1) {
        uint32_t o0, o1;
        threefry_0_42(0u, (uint32_t)i, o0, o1);
        g_v1[i] = bits_to_normal(o0 ^ o1);
    } else if (i < SZ1 + SZ2) {
        int j = i - SZ1;
        uint32_t o0, o1;
        threefry_0_42(0u, (uint32_t)j, o0, o1);
        g_v2[j] = bits_to_normal(o0 ^ o1);
    }
}

// ---------------------------------------------------------------------------
// 2) Column inverse norms (axis=0), plus loss-accumulator zero
// ---------------------------------------------------------------------------
__global__ void colnorms_kernel() {
    int t = threadIdx.x;   // 768 threads
    if (t == 0) g_loss = 0.0f;
    float s = 0.0f;
    if (t < TT) {
        #pragma unroll 8
        for (int k = 0; k < D1; k++) {
            float v = g_v1[k * TT + t];
            s = fmaf(v, v, s);
        }
        g_invnorm[t] = 1.0f / sqrtf(s);
    } else {
        int tt = t - TT;
        #pragma unroll 8
        for (int k = 0; k < D2; k++) {
            float v = g_v2[k * TT + tt];
            s = fmaf(v, v, s);
        }
        g_invnorm[t] = 1.0f / sqrtf(s);
    }
}

// ---------------------------------------------------------------------------
// 3) nh^T[t][n] = invnorm[t] * sum_k X[n,k] * V[k,t]   (tiled fp32 GEMM)
//    blockIdx.z: 0 -> space1 (D=128), 1 -> space2 (D=32)
// ---------------------------------------------------------------------------
__global__ void gemm_kernel(const float* __restrict__ s1,
                            const float* __restrict__ s2) {
    int space = blockIdx.z;
    const float* X = space ? s2 : s1;
    const float* V = space ? g_v2 : g_v1;
    float* OUT     = space ? g_nh2 : g_nh1;
    const int D    = space ? D2 : D1;
    const int inb  = space ? TT : 0;

    int n0 = blockIdx.x * 32;
    int t0 = blockIdx.y * 32;
    int tx = threadIdx.x;   // n within tile
    int ty = threadIdx.y;   // t within tile

    __shared__ float xs[32][33];   // [n][k], padded
    __shared__ float vs[32][33];   // [k][t]

    float acc = 0.0f;
    for (int k0 = 0; k0 < D; k0 += 32) {
        xs[ty][tx] = X[(n0 + ty) * D + (k0 + tx)];
        vs[ty][tx] = V[(k0 + ty) * TT + (t0 + tx)];
        __syncthreads();
        #pragma unroll
        for (int k = 0; k < 32; k++)
            acc = fmaf(xs[tx][k], vs[k][ty], acc);
        __syncthreads();
    }
    acc *= g_invnorm[inb + t0 + ty];
    OUT[(t0 + ty) * NN + (n0 + tx)] = acc;
}

// ---------------------------------------------------------------------------
// 4) ECT + loss. One block per direction t; thread = point n (both spaces).
//    sigmoid(500*(lin_r - nh)) is ~0/1 outside |lin_r - nh| <= 13/500:
//      - explicit sigmoid for the ~11-bin window (smem float atomics)
//      - "+1 for all r >= window_hi+1" via counter + block prefix sum
// ---------------------------------------------------------------------------
__device__ __forceinline__ void ect_accum(float nh, float* acc, int* cnt) {
    const float H  = 2.0f / 383.0f;       // lin spacing
    const float AI = 383.0f / 2.0f;       // 1/H
    const float BW = 13.0f * 383.0f / 1000.0f;  // 13/(500*H) = 4.979

    float a  = (nh + 1.0f) * AI;          // fractional crossing index
    int rlo  = (int)ceilf(a - BW);
    int rhi  = (int)floorf(a + BW);
    int c    = rhi + 1;
    if (c < 0) c = 0;
    if (c <= RR - 1) atomicAdd(&cnt[c], 1);   // all r >= c get +1
    int lo = rlo < 0 ? 0 : rlo;
    int hi = rhi > RR - 1 ? RR - 1 : rhi;
    for (int r = lo; r <= hi; r++) {
        float lin = fmaf((float)r, H, -1.0f);
        float z   = SCALE * (lin - nh);
        float sgm = 1.0f / (1.0f + __expf(-z));
        atomicAdd(&acc[r], sgm);
    }
}

__global__ void __launch_bounds__(384) ect_loss_kernel() {
    int t   = blockIdx.x;
    int tid = threadIdx.x;
    int lane = tid & 31, wid = tid >> 5;   // 12 warps

    __shared__ float acc1[RR], acc2[RR];
    __shared__ int   cnt1[RR + 1], cnt2[RR + 1];
    __shared__ int   wsum1[12], wsum2[12];
    __shared__ int   wofs1[12], wofs2[12];
    __shared__ float ps[12];

    acc1[tid] = 0.0f; acc2[tid] = 0.0f;
    cnt1[tid] = 0;    cnt2[tid] = 0;
    if (tid == 0) { cnt1[RR] = 0; cnt2[RR] = 0; }
    __syncthreads();

    // thread tid handles point n = tid for both spaces (coalesced reads)
    ect_accum(g_nh1[t * NN + tid], acc1, cnt1);
    ect_accum(g_nh2[t * NN + tid], acc2, cnt2);
    __syncthreads();

    // inclusive block scan of cnt1/cnt2 over r = tid
    int v1 = cnt1[tid], v2 = cnt2[tid];
    #pragma unroll
    for (int o = 1; o < 32; o <<= 1) {
        int y1 = __shfl_up_sync(0xffffffffu, v1, o);
        int y2 = __shfl_up_sync(0xffffffffu, v2, o);
        if (lane >= o) { v1 += y1; v2 += y2; }
    }
    if (lane == 31) { wsum1[wid] = v1; wsum2[wid] = v2; }
    __syncthreads();
    if (tid < 32) {
        int a1 = (tid < 12) ? wsum1[tid] : 0;
        int a2 = (tid < 12) ? wsum2[tid] : 0;
        #pragma unroll
        for (int o = 1; o < 32; o <<= 1) {
            int y1 = __shfl_up_sync(0xffffffffu, a1, o);
            int y2 = __shfl_up_sync(0xffffffffu, a2, o);
            if (tid >= o) { a1 += y1; a2 += y2; }
        }
        if (tid < 12) { wofs1[tid] = a1; wofs2[tid] = a2; }  // inclusive warp offsets
    }
    __syncthreads();
    int p1 = v1 + (wid ? wofs1[wid - 1] : 0);
    int p2 = v2 + (wid ? wofs2[wid - 1] : 0);

    float ect1 = acc1[tid] + (float)p1;
    float ect2 = acc2[tid] + (float)p2;
    float d    = ect1 - ect2;
    float sq   = d * d;

    // block reduce
    #pragma unroll
    for (int o = 16; o; o >>= 1) sq += __shfl_down_sync(0xffffffffu, sq, o);
    if (lane == 0) ps[wid] = sq;
    __syncthreads();
    if (tid == 0) {
        float s = 0.0f;
        #pragma unroll
        for (int i = 0; i < 12; i++) s += ps[i];
        atomicAdd(&g_loss, s);
    }
}

// ---------------------------------------------------------------------------
// 5) finalize: mean
// ---------------------------------------------------------------------------
__global__ void finalize_kernel(float* out) {
    out[0] = g_loss * (1.0f / (float)(RR * TT));
}

extern "C" void kernel_launch(void* const* d_in, const int* in_sizes, int n_in,
                              void* d_out, int out_size) {
    const float* s1 = (const float*)d_in[0];   // [384, 128]
    const float* s2 = (const float*)d_in[1];   // [384, 32]
    float* out = (float*)d_out;

    int total = SZ1 + SZ2;                     // 61440 elements
    gen_dirs_kernel<<<(total + 255) / 256, 256>>>();
    colnorms_kernel<<<1, 2 * TT>>>();
    gemm_kernel<<<dim3(NN / 32, TT / 32, 2), dim3(32, 32)>>>(s1, s2);
    ect_loss_kernel<<<TT, NN>>>();
    finalize_kernel<<<1, 1>>>(out);
}

// round 3
// speedup vs baseline: 1.2771x; 1.2771x over previous
#include <cuda_runtime.h>
#include <stdint.h>

// Problem constants
#define TT   384      // num_thetas (= n1 = n2)
#define NN   384      // points per space
#define RR   384      // resolution
#define D1   128
#define D2   32
#define SZ1  (D1*TT)  // 49152
#define SZ2  (D2*TT)  // 12288
#define SCALE 500.0f

// Scratch (static device globals; no allocation allowed)
__device__ float g_v1[SZ1];
__device__ float g_v2[SZ2];
__device__ float g_nh1[TT*NN];   // transposed: [t][n]
__device__ float g_nh2[TT*NN];
__device__ float g_loss;
__device__ unsigned int g_done = 0;

// ---------------------------------------------------------------------------
// Threefry2x32, key = (0, 42)  (jax.random.key(42)), partitionable layout
// ---------------------------------------------------------------------------
__device__ __forceinline__ uint32_t rotl32(uint32_t x, int d) {
    return (x << d) | (x >> (32 - d));
}

__device__ __forceinline__ void threefry_0_42(uint32_t x0, uint32_t x1,
                                              uint32_t& o0, uint32_t& o1) {
    const uint32_t ks0 = 0u;
    const uint32_t ks1 = 42u;
    const uint32_t ks2 = 0u ^ 42u ^ 0x1BD11BDAu;
    x0 += ks0; x1 += ks1;
#define TF_R4(a,b,c,d)                               \
    x0 += x1; x1 = rotl32(x1,(a)); x1 ^= x0;          \
    x0 += x1; x1 = rotl32(x1,(b)); x1 ^= x0;          \
    x0 += x1; x1 = rotl32(x1,(c)); x1 ^= x0;          \
    x0 += x1; x1 = rotl32(x1,(d)); x1 ^= x0;
    TF_R4(13,15,26,6)   x0 += ks1; x1 += ks2 + 1u;
    TF_R4(17,29,16,24)  x0 += ks2; x1 += ks0 + 2u;
    TF_R4(13,15,26,6)   x0 += ks0; x1 += ks1 + 3u;
    TF_R4(17,29,16,24)  x0 += ks1; x1 += ks2 + 4u;
    TF_R4(13,15,26,6)   x0 += ks2; x1 += ks0 + 5u;
#undef TF_R4
    o0 = x0; o1 = x1;
}

// XLA ErfInv (float32 polynomial) — matches lax.erf_inv lowering
__device__ __forceinline__ float erfinv_xla(float x) {
    float w = -log1pf(-x * x);
    float p;
    if (w < 5.0f) {
        w -= 2.5f;
        p = 2.81022636e-08f;
        p = fmaf(p, w, 3.43273939e-07f);
        p = fmaf(p, w, -3.5233877e-06f);
        p = fmaf(p, w, -4.39150654e-06f);
        p = fmaf(p, w, 0.00021858087f);
        p = fmaf(p, w, -0.00125372503f);
        p = fmaf(p, w, -0.00417768164f);
        p = fmaf(p, w, 0.246640727f);
        p = fmaf(p, w, 1.50140941f);
    } else {
        w = sqrtf(w) - 3.0f;
        p = -0.000200214257f;
        p = fmaf(p, w, 0.000100950558f);
        p = fmaf(p, w, 0.00134934322f);
        p = fmaf(p, w, -0.00367342844f);
        p = fmaf(p, w, 0.00573950773f);
        p = fmaf(p, w, -0.0076224613f);
        p = fmaf(p, w, 0.00943887047f);
        p = fmaf(p, w, 1.00167406f);
        p = fmaf(p, w, 2.83297682f);
    }
    return p * x;
}

__device__ __forceinline__ float bits_to_normal(uint32_t b) {
    float f = __uint_as_float((b >> 9) | 0x3F800000u) - 1.0f;   // [0,1)
    const float lo = -0.99999994f;                               // nextafter(-1,0)
    const float span = 1.0f - lo;
    float u = fmaf(f, span, lo);
    u = fmaxf(lo, u);
    return 1.41421356f * erfinv_xla(u);   // sqrt(2)
}

// ---------------------------------------------------------------------------
// 1) Generate direction matrices (partitionable threefry: bits = o0 ^ o1,
//    counter = (0, i)). Also resets the loss accumulator for graph replay.
// ---------------------------------------------------------------------------
__global__ void gen_dirs_kernel() {
    int i = blockIdx.x * blockDim.x + threadIdx.x;
    if (i == 0) g_loss = 0.0f;
    if (i < SZ1) {
        uint32_t o0, o1;
        threefry_0_42(0u, (uint32_t)i, o0, o1);
        g_v1[i] = bits_to_normal(o0 ^ o1);
    } else if (i < SZ1 + SZ2) {
        int j = i - SZ1;
        uint32_t o0, o1;
        threefry_0_42(0u, (uint32_t)j, o0, o1);
        g_v2[j] = bits_to_normal(o0 ^ o1);
    }
}

// ---------------------------------------------------------------------------
// 2) nh^T[t][n] = (sum_k X[n,k] V[k,t]) * rsqrt(sum_k V[k,t]^2)
//    Column norms computed in-block (each block sees its full V columns).
//    blockIdx.z: 0 -> space1 (D=128), 1 -> space2 (D=32)
// ---------------------------------------------------------------------------
__global__ void gemm_kernel(const float* __restrict__ s1,
                            const float* __restrict__ s2) {
    int space = blockIdx.z;
    const float* X = space ? s2 : s1;
    const float* V = space ? g_v2 : g_v1;
    float* OUT     = space ? g_nh2 : g_nh1;
    const int D    = space ? D2 : D1;

    int n0 = blockIdx.x * 32;
    int t0 = blockIdx.y * 32;
    int tx = threadIdx.x;   // n within tile (and t-in-tile for norm partials)
    int ty = threadIdx.y;

    __shared__ float xs[32][33];   // [n][k]
    __shared__ float vs[32][33];   // [k][t]
    __shared__ float nrm[32];
    __shared__ float inv[32];

    if (ty == 0) nrm[tx] = 0.0f;

    float acc  = 0.0f;
    float nsum = 0.0f;             // partial of sum_k V[k, t0+tx]^2 over k = k0+ty
    for (int k0 = 0; k0 < D; k0 += 32) {
        float v = V[(k0 + ty) * TT + (t0 + tx)];
        xs[ty][tx] = X[(n0 + ty) * D + (k0 + tx)];
        vs[ty][tx] = v;
        nsum = fmaf(v, v, nsum);
        __syncthreads();
        #pragma unroll
        for (int k = 0; k < 32; k++)
            acc = fmaf(xs[tx][k], vs[k][ty], acc);
        __syncthreads();
    }
    atomicAdd(&nrm[tx], nsum);
    __syncthreads();
    if (ty == 0) inv[tx] = rsqrtf(nrm[tx]);
    __syncthreads();

    OUT[(t0 + ty) * NN + (n0 + tx)] = acc * inv[ty];
}

// ---------------------------------------------------------------------------
// 3) ECT + loss + finalize. One block per direction t; thread = point n.
//    sigmoid via hardware tanh: sig(z) = 0.5 + 0.5*tanh(z/2).
//    Window |z| <= 8 (~6 bins); "+1 for all r above window" via counter
//    + block prefix-sum.
// ---------------------------------------------------------------------------
__device__ __forceinline__ float tanh_hw(float x) {
    float y;
    asm("tanh.approx.f32 %0, %1;" : "=f"(y) : "f"(x));
    return y;
}

__device__ __forceinline__ void ect_accum(float nh, float* acc, int* cnt) {
    const float H   = 2.0f / 383.0f;
    const float AI  = 383.0f / 2.0f;
    const float BW  = 8.0f * 383.0f / 1000.0f;   // 8/(500*H) = 3.064
    const float H250 = 500.0f / 383.0f;          // 250*H

    float a  = (nh + 1.0f) * AI;
    int rlo  = (int)ceilf(a - BW);
    int rhi  = (int)floorf(a + BW);
    int c    = rhi + 1;
    if (c < 0) c = 0;
    if (c <= RR - 1) atomicAdd(&cnt[c], 1);
    int lo = rlo < 0 ? 0 : rlo;
    int hi = rhi > RR - 1 ? RR - 1 : rhi;
    float b = -250.0f * (1.0f + nh);             // z/2 at r=0
    for (int r = lo; r <= hi; r++) {
        float z2  = fmaf((float)r, H250, b);
        float sgm = fmaf(0.5f, tanh_hw(z2), 0.5f);
        atomicAdd(&acc[r], sgm);
    }
}

__global__ void __launch_bounds__(384) ect_loss_kernel(float* __restrict__ out) {
    int t    = blockIdx.x;
    int tid  = threadIdx.x;
    int lane = tid & 31, wid = tid >> 5;   // 12 warps

    __shared__ float acc1[RR], acc2[RR];
    __shared__ int   cnt1[RR], cnt2[RR];
    __shared__ int   wsum1[12], wsum2[12];
    __shared__ int   wofs1[12], wofs2[12];
    __shared__ float ps[12];

    acc1[tid] = 0.0f; acc2[tid] = 0.0f;
    cnt1[tid] = 0;    cnt2[tid] = 0;
    __syncthreads();

    ect_accum(g_nh1[t * NN + tid], acc1, cnt1);
    ect_accum(g_nh2[t * NN + tid], acc2, cnt2);
    __syncthreads();

    // inclusive block scan of counters over r = tid
    int v1 = cnt1[tid], v2 = cnt2[tid];
    #pragma unroll
    for (int o = 1; o < 32; o <<= 1) {
        int y1 = __shfl_up_sync(0xffffffffu, v1, o);
        int y2 = __shfl_up_sync(0xffffffffu, v2, o);
        if (lane >= o) { v1 += y1; v2 += y2; }
    }
    if (lane == 31) { wsum1[wid] = v1; wsum2[wid] = v2; }
    __syncthreads();
    if (tid < 32) {
        int a1 = (tid < 12) ? wsum1[tid] : 0;
        int a2 = (tid < 12) ? wsum2[tid] : 0;
        #pragma unroll
        for (int o = 1; o < 32; o <<= 1) {
            int y1 = __shfl_up_sync(0xffffffffu, a1, o);
            int y2 = __shfl_up_sync(0xffffffffu, a2, o);
            if (tid >= o) { a1 += y1; a2 += y2; }
        }
        if (tid < 12) { wofs1[tid] = a1; wofs2[tid] = a2; }
    }
    __syncthreads();
    int p1 = v1 + (wid ? wofs1[wid - 1] : 0);
    int p2 = v2 + (wid ? wofs2[wid - 1] : 0);

    float d  = (acc1[tid] + (float)p1) - (acc2[tid] + (float)p2);
    float sq = d * d;

    #pragma unroll
    for (int o = 16; o; o >>= 1) sq += __shfl_down_sync(0xffffffffu, sq, o);
    if (lane == 0) ps[wid] = sq;
    __syncthreads();
    if (tid == 0) {
        float s = 0.0f;
        #pragma unroll
        for (int i = 0; i < 12; i++) s += ps[i];
        atomicAdd(&g_loss, s);
        __threadfence();
        unsigned prev = atomicAdd(&g_done, 1u);
        if (prev == (unsigned)(gridDim.x - 1)) {
            g_done = 0u;  // self-reset for graph replay
            float total = *((volatile float*)&g_loss);
            out[0] = total * (1.0f / (float)(RR * TT));
        }
    }
}

extern "C" void kernel_launch(void* const* d_in, const int* in_sizes, int n_in,
                              void* d_out, int out_size) {
    const float* s1 = (const float*)d_in[0];   // [384, 128]
    const float* s2 = (const float*)d_in[1];   // [384, 32]
    float* out = (float*)d_out;

    int total = SZ1 + SZ2;                     // 61440
    gen_dirs_kernel<<<(total + 255) / 256, 256>>>();
    gemm_kernel<<<dim3(NN / 32, TT / 32, 2), dim3(32, 32)>>>(s1, s2);
    ect_loss_kernel<<<TT, NN>>>(out);
}